// round 1
// baseline (speedup 1.0000x reference)
#include <cuda_runtime.h>

// Ragged segment mean: out[b,d] = mean(seq[b, begin[b]:end[b], d])
// B=2048, L=512, D=512, fp32.
// One CTA per batch. 128 threads; thread t owns float4 column t (D/4 = 128).
// Coalesced 2KB-per-row streaming loads; register accumulation; single store.

static constexpr int L_DIM = 512;
static constexpr int D_DIM = 512;
static constexpr int D_VEC = D_DIM / 4;   // 128 float4 per row

__global__ __launch_bounds__(128) void ragged_mean_kernel(
    const float* __restrict__ seq,
    const int*   __restrict__ begin,
    const int*   __restrict__ end,
    float*       __restrict__ out)
{
    const int b = blockIdx.x;
    const int t = threadIdx.x;            // 0..127

    const int s = begin[b];
    const int e = end[b];

    // base pointer to float4 column t of batch b
    const float4* __restrict__ base =
        reinterpret_cast<const float4*>(seq) + (size_t)b * L_DIM * D_VEC + t;

    float ax = 0.f, ay = 0.f, az = 0.f, aw = 0.f;

    int l = s;
    // 4-row unroll for MLP
    for (; l + 4 <= e; l += 4) {
        float4 v0 = base[(size_t)(l + 0) * D_VEC];
        float4 v1 = base[(size_t)(l + 1) * D_VEC];
        float4 v2 = base[(size_t)(l + 2) * D_VEC];
        float4 v3 = base[(size_t)(l + 3) * D_VEC];
        ax += v0.x; ay += v0.y; az += v0.z; aw += v0.w;
        ax += v1.x; ay += v1.y; az += v1.z; aw += v1.w;
        ax += v2.x; ay += v2.y; az += v2.z; aw += v2.w;
        ax += v3.x; ay += v3.y; az += v3.z; aw += v3.w;
    }
    for (; l < e; ++l) {
        float4 v = base[(size_t)l * D_VEC];
        ax += v.x; ay += v.y; az += v.z; aw += v.w;
    }

    const float inv = 1.0f / (float)(e - s);
    float4 r;
    r.x = ax * inv; r.y = ay * inv; r.z = az * inv; r.w = aw * inv;

    reinterpret_cast<float4*>(out)[(size_t)b * D_VEC + t] = r;
}

extern "C" void kernel_launch(void* const* d_in, const int* in_sizes, int n_in,
                              void* d_out, int out_size)
{
    const float* seq   = (const float*)d_in[0];
    const int*   begin = (const int*)d_in[1];
    const int*   end   = (const int*)d_in[2];
    float*       out   = (float*)d_out;

    const int B = in_sizes[1];   // 2048 batches (element count of begin)

    ragged_mean_kernel<<<B, 128>>>(seq, begin, end, out);
}